// round 1
// baseline (speedup 1.0000x reference)
#include <cuda_runtime.h>
#include <math.h>

// Flow_49546742727298: CNF Euler integrator, exact divergence via analytic trace.
// x: [B,16], W1: [17,64], b1: [64], W2: [64,16], b2: [16]
// Per step: h = tanh([x,t]@W1 + b1); v = h@W2 + b2; div = sum_j (1-h_j^2)*c_j
// with c_j = sum_i W1[i,j]*W2[j,i]  (trace of W1^T diag(1-h^2) W2).
// x += dt*v; logq -= dt*div.  dt = 0.5, t in {0, 0.5}.

#define BATCH_THREADS 256
#define NSTEPS 2

// Packed per-hidden-unit row in shared memory (36 floats, 144B, 16B-aligned):
//   [0..15]  W1[i][j] for i = 0..15   (x weights, column j)
//   [16]     W1[16][j]                (t weight)
//   [17]     b1[j]
//   [18]     c[j] = sum_i W1[i][j]*W2[j][i]
//   [19]     pad
//   [20..35] W2[j][0..15]
#define ROWF 36

__global__ void __launch_bounds__(BATCH_THREADS)
flow_kernel(const float* __restrict__ x0,
            const float* __restrict__ W1,   // [17*64] row-major
            const float* __restrict__ b1,   // [64]
            const float* __restrict__ W2,   // [64*16] row-major
            const float* __restrict__ b2,   // [16]
            float* __restrict__ out,        // [B*16] x1, then [B] dlogq
            int batch)
{
    __shared__ __align__(16) float sp[64 * ROWF];
    __shared__ float sb2[16];

    const int tid = threadIdx.x;

    // Cooperative fill of the packed weight rows (one-time, tiny).
    if (tid < 64) {
        const int j = tid;
        float* row = &sp[j * ROWF];
        float c = 0.f;
        #pragma unroll
        for (int i = 0; i < 16; i++) {
            float w1 = W1[i * 64 + j];
            float w2 = W2[j * 16 + i];
            row[i]      = w1;
            row[20 + i] = w2;
            c += w1 * w2;
        }
        row[16] = W1[16 * 64 + j];
        row[17] = b1[j];
        row[18] = c;
        row[19] = 0.f;
    } else if (tid < 80) {
        sb2[tid - 64] = b2[tid - 64];
    }
    __syncthreads();

    const int b = blockIdx.x * BATCH_THREADS + tid;
    if (b >= batch) return;

    // Load x (16 floats) as 4x float4, coalesced.
    float x[16];
    #pragma unroll
    for (int q = 0; q < 4; q++) {
        float4 t4 = reinterpret_cast<const float4*>(x0)[b * 4 + q];
        x[q * 4 + 0] = t4.x; x[q * 4 + 1] = t4.y;
        x[q * 4 + 2] = t4.z; x[q * 4 + 3] = t4.w;
    }

    float logq = 0.f;
    const float dt = 0.5f;

    #pragma unroll
    for (int s = 0; s < NSTEPS; s++) {
        const float t = dt * (float)s;
        float v[16];
        #pragma unroll
        for (int i = 0; i < 16; i++) v[i] = sb2[i];
        float div = 0.f;

        #pragma unroll 4
        for (int j = 0; j < 64; j++) {
            const float4* row4 = reinterpret_cast<const float4*>(&sp[j * ROWF]);
            // W1 column (x weights) + [wt, b1, c, pad]
            float4 a0 = row4[0];
            float4 a1 = row4[1];
            float4 a2 = row4[2];
            float4 a3 = row4[3];
            float4 a4 = row4[4];   // x: t-weight, y: b1, z: c, w: pad

            float pre = fmaf(t, a4.x, a4.y);
            pre = fmaf(x[ 0], a0.x, pre); pre = fmaf(x[ 1], a0.y, pre);
            pre = fmaf(x[ 2], a0.z, pre); pre = fmaf(x[ 3], a0.w, pre);
            pre = fmaf(x[ 4], a1.x, pre); pre = fmaf(x[ 5], a1.y, pre);
            pre = fmaf(x[ 6], a1.z, pre); pre = fmaf(x[ 7], a1.w, pre);
            pre = fmaf(x[ 8], a2.x, pre); pre = fmaf(x[ 9], a2.y, pre);
            pre = fmaf(x[10], a2.z, pre); pre = fmaf(x[11], a2.w, pre);
            pre = fmaf(x[12], a3.x, pre); pre = fmaf(x[13], a3.y, pre);
            pre = fmaf(x[14], a3.z, pre); pre = fmaf(x[15], a3.w, pre);

            float h = tanhf(pre);
            div = fmaf(1.f - h * h, a4.z, div);

            float4 w0 = row4[5];
            float4 w1 = row4[6];
            float4 w2 = row4[7];
            float4 w3 = row4[8];
            v[ 0] = fmaf(h, w0.x, v[ 0]); v[ 1] = fmaf(h, w0.y, v[ 1]);
            v[ 2] = fmaf(h, w0.z, v[ 2]); v[ 3] = fmaf(h, w0.w, v[ 3]);
            v[ 4] = fmaf(h, w1.x, v[ 4]); v[ 5] = fmaf(h, w1.y, v[ 5]);
            v[ 6] = fmaf(h, w1.z, v[ 6]); v[ 7] = fmaf(h, w1.w, v[ 7]);
            v[ 8] = fmaf(h, w2.x, v[ 8]); v[ 9] = fmaf(h, w2.y, v[ 9]);
            v[10] = fmaf(h, w2.z, v[10]); v[11] = fmaf(h, w2.w, v[11]);
            v[12] = fmaf(h, w3.x, v[12]); v[13] = fmaf(h, w3.y, v[13]);
            v[14] = fmaf(h, w3.z, v[14]); v[15] = fmaf(h, w3.w, v[15]);
        }

        #pragma unroll
        for (int i = 0; i < 16; i++) x[i] = fmaf(dt, v[i], x[i]);
        logq -= dt * div;
    }

    // Store x1 (coalesced float4) and dlogq.
    #pragma unroll
    for (int q = 0; q < 4; q++) {
        float4 t4 = make_float4(x[q * 4 + 0], x[q * 4 + 1],
                                x[q * 4 + 2], x[q * 4 + 3]);
        reinterpret_cast<float4*>(out)[b * 4 + q] = t4;
    }
    out[(size_t)batch * 16 + b] = logq;
}

extern "C" void kernel_launch(void* const* d_in, const int* in_sizes, int n_in,
                              void* d_out, int out_size) {
    const float* x0 = (const float*)d_in[0];
    const float* W1 = (const float*)d_in[1];
    const float* b1 = (const float*)d_in[2];
    const float* W2 = (const float*)d_in[3];
    const float* b2 = (const float*)d_in[4];
    float* out = (float*)d_out;

    const int batch = in_sizes[0] / 16;  // x0 is [B,16]
    const int blocks = (batch + BATCH_THREADS - 1) / BATCH_THREADS;
    flow_kernel<<<blocks, BATCH_THREADS>>>(x0, W1, b1, W2, b2, out, batch);
}

// round 2
// speedup vs baseline: 1.2455x; 1.2455x over previous
#include <cuda_runtime.h>
#include <math.h>

// Flow_49546742727298: CNF Euler, exact divergence via analytic trace.
// R2: f32x2 packed FMAs (i-dimension pairs), 2 samples/thread, ex2/rcp tanh.

#define THREADS 256
#define MSAMP   2
#define NSTEPS  2
#define ROWF    36   // floats per packed weight row (144B, 16B-aligned)

typedef unsigned long long u64;

__device__ __forceinline__ u64 fma2(u64 a, u64 b, u64 c) {
    u64 d; asm("fma.rn.f32x2 %0, %1, %2, %3;" : "=l"(d) : "l"(a), "l"(b), "l"(c)); return d;
}
__device__ __forceinline__ u64 mul2(u64 a, u64 b) {
    u64 d; asm("mul.rn.f32x2 %0, %1, %2;" : "=l"(d) : "l"(a), "l"(b)); return d;
}
__device__ __forceinline__ u64 pack2(float lo, float hi) {
    u64 d; asm("mov.b64 %0, {%1, %2};" : "=l"(d) : "f"(lo), "f"(hi)); return d;
}
__device__ __forceinline__ void unpack2(u64 p, float& lo, float& hi) {
    asm("mov.b64 {%0, %1}, %2;" : "=f"(lo), "=f"(hi) : "l"(p));
}
__device__ __forceinline__ float ex2f(float x) {
    float y; asm("ex2.approx.f32 %0, %1;" : "=f"(y) : "f"(x)); return y;
}
__device__ __forceinline__ float rcpf(float x) {
    float y; asm("rcp.approx.f32 %0, %1;" : "=f"(y) : "f"(x)); return y;
}
// tanh(x) = (e^{2x}-1)/(e^{2x}+1); abs err ~1e-7 (MUFU ex2+rcp are near-exact).
__device__ __forceinline__ float fast_tanh(float x) {
    float t = ex2f(x * 2.885390081777927f);   // 2*log2(e)
    float r = rcpf(t + 1.0f);
    return fmaf(t, r, -r);                    // (t-1)*r
}

// Shared row j (36 floats):
//  [0..15]  W1[0..15][j]  (i-pairs are consecutive -> packed u64 operands)
//  [16] W1[16][j] (t-weight)  [17] b1[j]  [18] c[j]=sum_i W1[i][j]*W2[j][i]  [19] pad
//  [20..35] W2[j][0..15]      (pairs consecutive -> packed u64 operands)

__global__ void __launch_bounds__(THREADS)
flow_kernel(const float* __restrict__ x0,
            const float* __restrict__ W1,
            const float* __restrict__ b1,
            const float* __restrict__ W2,
            const float* __restrict__ b2,
            float* __restrict__ out,
            int batch)
{
    __shared__ __align__(16) float sp[64 * ROWF];
    __shared__ __align__(16) float sb2[16];

    const int tid = threadIdx.x;

    if (tid < 64) {
        const int j = tid;
        float* row = &sp[j * ROWF];
        float c = 0.f;
        #pragma unroll
        for (int i = 0; i < 16; i++) {
            float w1 = W1[i * 64 + j];
            float w2 = W2[j * 16 + i];
            row[i]      = w1;
            row[20 + i] = w2;
            c += w1 * w2;
        }
        row[16] = W1[16 * 64 + j];
        row[17] = b1[j];
        row[18] = c;
        row[19] = 0.f;
    } else if (tid < 80) {
        sb2[tid - 64] = b2[tid - 64];
    }
    __syncthreads();

    // Two samples per thread: coalesced halves of a 512-sample block tile.
    const int base = blockIdx.x * (THREADS * MSAMP);
    int bs[MSAMP];
    bs[0] = base + tid;
    bs[1] = base + THREADS + tid;
    if (bs[0] >= batch) return;
    const bool has1 = (bs[1] < batch);

    // x packed: X[m][k] = (x[2k], x[2k+1]) as f32x2
    u64 X[MSAMP][8];
    const ulonglong2* xin = (const ulonglong2*)x0;
    #pragma unroll
    for (int m = 0; m < MSAMP; m++) {
        int b = (m == 0 || has1) ? bs[m] : bs[0];
        #pragma unroll
        for (int q = 0; q < 4; q++) {
            ulonglong2 t2 = xin[(size_t)b * 4 + q];
            X[m][2 * q]     = t2.x;
            X[m][2 * q + 1] = t2.y;
        }
    }

    // b2 packed, kept in registers
    u64 B2r[8];
    #pragma unroll
    for (int k = 0; k < 8; k++) B2r[k] = ((const u64*)sb2)[k];

    const float dt = 0.5f;
    const u64 dt2 = pack2(dt, dt);
    float logq[MSAMP] = {0.f, 0.f};

    #pragma unroll
    for (int s = 0; s < NSTEPS; s++) {
        const float t_ = dt * (float)s;
        u64 V[MSAMP][8];
        #pragma unroll
        for (int m = 0; m < MSAMP; m++)
            #pragma unroll
            for (int k = 0; k < 8; k++) V[m][k] = B2r[k];
        float dv[MSAMP] = {0.f, 0.f};

        #pragma unroll 4
        for (int j = 0; j < 64; j++) {
            const ulonglong2* rp = (const ulonglong2*)&sp[j * ROWF];
            ulonglong2 wa = rp[0];          // W1 pairs i0..3
            ulonglong2 wb = rp[1];          // i4..7
            ulonglong2 wc = rp[2];          // i8..11
            ulonglong2 wd = rp[3];          // i12..15
            float4 aux = ((const float4*)rp)[4];   // wt, b1, c, pad
            ulonglong2 va = rp[5];          // W2 pairs
            ulonglong2 vb = rp[6];
            ulonglong2 vc = rp[7];
            ulonglong2 vd = rp[8];

            const float bse = fmaf(t_, aux.x, aux.y);

            #pragma unroll
            for (int m = 0; m < MSAMP; m++) {
                u64 p = mul2(X[m][0], wa.x);
                p = fma2(X[m][1], wa.y, p);
                p = fma2(X[m][2], wb.x, p);
                p = fma2(X[m][3], wb.y, p);
                p = fma2(X[m][4], wc.x, p);
                p = fma2(X[m][5], wc.y, p);
                p = fma2(X[m][6], wd.x, p);
                p = fma2(X[m][7], wd.y, p);
                float lo, hi; unpack2(p, lo, hi);
                float pre = (lo + hi) + bse;
                float h = fast_tanh(pre);
                dv[m] = fmaf(fmaf(-h, h, 1.f), aux.z, dv[m]);
                u64 h2 = pack2(h, h);
                V[m][0] = fma2(h2, va.x, V[m][0]);
                V[m][1] = fma2(h2, va.y, V[m][1]);
                V[m][2] = fma2(h2, vb.x, V[m][2]);
                V[m][3] = fma2(h2, vb.y, V[m][3]);
                V[m][4] = fma2(h2, vc.x, V[m][4]);
                V[m][5] = fma2(h2, vc.y, V[m][5]);
                V[m][6] = fma2(h2, vd.x, V[m][6]);
                V[m][7] = fma2(h2, vd.y, V[m][7]);
            }
        }

        #pragma unroll
        for (int m = 0; m < MSAMP; m++) {
            #pragma unroll
            for (int k = 0; k < 8; k++) X[m][k] = fma2(dt2, V[m][k], X[m][k]);
            logq[m] -= dt * dv[m];
        }
    }

    // Store x1 (packed pairs = contiguous floats) and dlogq.
    ulonglong2* outp = (ulonglong2*)out;
    #pragma unroll
    for (int m = 0; m < MSAMP; m++) {
        if (m == 1 && !has1) break;
        const int b = bs[m];
        #pragma unroll
        for (int q = 0; q < 4; q++) {
            ulonglong2 t2;
            t2.x = X[m][2 * q];
            t2.y = X[m][2 * q + 1];
            outp[(size_t)b * 4 + q] = t2;
        }
        out[(size_t)batch * 16 + b] = logq[m];
    }
}

extern "C" void kernel_launch(void* const* d_in, const int* in_sizes, int n_in,
                              void* d_out, int out_size) {
    const float* x0 = (const float*)d_in[0];
    const float* W1 = (const float*)d_in[1];
    const float* b1 = (const float*)d_in[2];
    const float* W2 = (const float*)d_in[3];
    const float* b2 = (const float*)d_in[4];
    float* out = (float*)d_out;

    const int batch = in_sizes[0] / 16;
    const int per_block = THREADS * MSAMP;
    const int blocks = (batch + per_block - 1) / per_block;
    flow_kernel<<<blocks, THREADS>>>(x0, W1, b1, W2, b2, out, batch);
}

// round 3
// speedup vs baseline: 1.4531x; 1.1667x over previous
#include <cuda_runtime.h>
#include <math.h>

// Flow_49546742727298: CNF Euler, exact divergence via analytic trace.
// R3: MUFU.TANH, split pre-activation chains, lower reg pressure.

#define THREADS 256
#define MSAMP   2
#define NSTEPS  2
#define ROWF    36

typedef unsigned long long u64;

__device__ __forceinline__ u64 fma2(u64 a, u64 b, u64 c) {
    u64 d; asm("fma.rn.f32x2 %0, %1, %2, %3;" : "=l"(d) : "l"(a), "l"(b), "l"(c)); return d;
}
__device__ __forceinline__ u64 mul2(u64 a, u64 b) {
    u64 d; asm("mul.rn.f32x2 %0, %1, %2;" : "=l"(d) : "l"(a), "l"(b)); return d;
}
__device__ __forceinline__ u64 add2(u64 a, u64 b) {
    u64 d; asm("add.rn.f32x2 %0, %1, %2;" : "=l"(d) : "l"(a), "l"(b)); return d;
}
__device__ __forceinline__ u64 pack2(float lo, float hi) {
    u64 d; asm("mov.b64 %0, {%1, %2};" : "=l"(d) : "f"(lo), "f"(hi)); return d;
}
__device__ __forceinline__ void unpack2(u64 p, float& lo, float& hi) {
    asm("mov.b64 {%0, %1}, %2;" : "=f"(lo), "=f"(hi) : "l"(p));
}
// HW tanh (MUFU.TANH), 1 instruction, rel err ~5e-4 worst case.
__device__ __forceinline__ float fast_tanh(float x) {
    float y; asm("tanh.approx.f32 %0, %1;" : "=f"(y) : "f"(x)); return y;
}

// Shared row j (36 floats, 144B):
//  [0..15]  W1[0..15][j]   (i-pairs consecutive -> u64 f32x2 operands)
//  [16] W1[16][j]  [17] b1[j]  [18] c[j]=sum_i W1[i][j]*W2[j][i]  [19] pad
//  [20..35] W2[j][0..15]

__global__ void __launch_bounds__(THREADS)
flow_kernel(const float* __restrict__ x0,
            const float* __restrict__ W1,
            const float* __restrict__ b1,
            const float* __restrict__ W2,
            const float* __restrict__ b2,
            float* __restrict__ out,
            int batch)
{
    __shared__ __align__(16) float sp[64 * ROWF];
    __shared__ __align__(16) float sb2[16];

    const int tid = threadIdx.x;

    if (tid < 64) {
        const int j = tid;
        float* row = &sp[j * ROWF];
        float c = 0.f;
        #pragma unroll
        for (int i = 0; i < 16; i++) {
            float w1 = W1[i * 64 + j];
            float w2 = W2[j * 16 + i];
            row[i]      = w1;
            row[20 + i] = w2;
            c += w1 * w2;
        }
        row[16] = W1[16 * 64 + j];
        row[17] = b1[j];
        row[18] = c;
        row[19] = 0.f;
    } else if (tid < 80) {
        sb2[tid - 64] = b2[tid - 64];
    }
    __syncthreads();

    const int base = blockIdx.x * (THREADS * MSAMP);
    int bs[MSAMP];
    bs[0] = base + tid;
    bs[1] = base + THREADS + tid;
    if (bs[0] >= batch) return;
    const bool has1 = (bs[1] < batch);

    u64 X[MSAMP][8];
    const ulonglong2* xin = (const ulonglong2*)x0;
    #pragma unroll
    for (int m = 0; m < MSAMP; m++) {
        int b = (m == 0 || has1) ? bs[m] : bs[0];
        #pragma unroll
        for (int q = 0; q < 4; q++) {
            ulonglong2 t2 = xin[(size_t)b * 4 + q];
            X[m][2 * q]     = t2.x;
            X[m][2 * q + 1] = t2.y;
        }
    }

    const float dt = 0.5f;
    const u64 dt2 = pack2(dt, dt);
    float logq[MSAMP] = {0.f, 0.f};
    const u64* sb2u = (const u64*)sb2;

    #pragma unroll
    for (int s = 0; s < NSTEPS; s++) {
        const float t_ = dt * (float)s;
        u64 V[MSAMP][8];
        #pragma unroll
        for (int m = 0; m < MSAMP; m++)
            #pragma unroll
            for (int k = 0; k < 8; k++) V[m][k] = sb2u[k];
        float dv[MSAMP] = {0.f, 0.f};

        #pragma unroll 4
        for (int j = 0; j < 64; j++) {
            const ulonglong2* rp = (const ulonglong2*)&sp[j * ROWF];
            ulonglong2 wa = rp[0];
            ulonglong2 wb = rp[1];
            ulonglong2 wc = rp[2];
            ulonglong2 wd = rp[3];
            float4 aux = ((const float4*)rp)[4];   // wt, b1, c, pad
            ulonglong2 va = rp[5];
            ulonglong2 vb = rp[6];
            ulonglong2 vc = rp[7];
            ulonglong2 vd = rp[8];

            const float bse = fmaf(t_, aux.x, aux.y);

            #pragma unroll
            for (int m = 0; m < MSAMP; m++) {
                // Two independent 4-deep chains instead of one 8-deep chain.
                u64 p0 = mul2(X[m][0], wa.x);
                u64 p1 = mul2(X[m][1], wa.y);
                p0 = fma2(X[m][2], wb.x, p0);
                p1 = fma2(X[m][3], wb.y, p1);
                p0 = fma2(X[m][4], wc.x, p0);
                p1 = fma2(X[m][5], wc.y, p1);
                p0 = fma2(X[m][6], wd.x, p0);
                p1 = fma2(X[m][7], wd.y, p1);
                u64 p = add2(p0, p1);
                float lo, hi; unpack2(p, lo, hi);
                float pre = (lo + hi) + bse;
                float h = fast_tanh(pre);
                float hh = h * h;
                dv[m] = fmaf(1.f - hh, aux.z, dv[m]);
                u64 h2 = pack2(h, h);
                V[m][0] = fma2(h2, va.x, V[m][0]);
                V[m][1] = fma2(h2, va.y, V[m][1]);
                V[m][2] = fma2(h2, vb.x, V[m][2]);
                V[m][3] = fma2(h2, vb.y, V[m][3]);
                V[m][4] = fma2(h2, vc.x, V[m][4]);
                V[m][5] = fma2(h2, vc.y, V[m][5]);
                V[m][6] = fma2(h2, vd.x, V[m][6]);
                V[m][7] = fma2(h2, vd.y, V[m][7]);
            }
        }

        #pragma unroll
        for (int m = 0; m < MSAMP; m++) {
            #pragma unroll
            for (int k = 0; k < 8; k++) X[m][k] = fma2(dt2, V[m][k], X[m][k]);
            logq[m] -= dt * dv[m];
        }
    }

    ulonglong2* outp = (ulonglong2*)out;
    #pragma unroll
    for (int m = 0; m < MSAMP; m++) {
        if (m == 1 && !has1) break;
        const int b = bs[m];
        #pragma unroll
        for (int q = 0; q < 4; q++) {
            ulonglong2 t2;
            t2.x = X[m][2 * q];
            t2.y = X[m][2 * q + 1];
            outp[(size_t)b * 4 + q] = t2;
        }
        out[(size_t)batch * 16 + b] = logq[m];
    }
}

extern "C" void kernel_launch(void* const* d_in, const int* in_sizes, int n_in,
                              void* d_out, int out_size) {
    const float* x0 = (const float*)d_in[0];
    const float* W1 = (const float*)d_in[1];
    const float* b1 = (const float*)d_in[2];
    const float* W2 = (const float*)d_in[3];
    const float* b2 = (const float*)d_in[4];
    float* out = (float*)d_out;

    const int batch = in_sizes[0] / 16;
    const int per_block = THREADS * MSAMP;
    const int blocks = (batch + per_block - 1) / per_block;
    flow_kernel<<<blocks, THREADS>>>(x0, W1, b1, W2, b2, out, batch);
}